// round 4
// baseline (speedup 1.0000x reference)
#include <cuda_runtime.h>
#include <cuda_bf16.h>
#include <cstdint>

// HungarianMatcher cost computation, block-diagonal only.
// Shapes: BS=16, Q=1000, NC=80, T=100, NI=8
// Output: C_diag (BS,Q,T) followed by ioa_diag (BS,Q,NI), f32.

#define BSZ 16
#define QN  1000
#define NC  80
#define TN  100
#define NIN 8
#define QPB 10   // q rows per block

__global__ __launch_bounds__(128, 10)
void matcher_kernel(const float* __restrict__ logits,
                    const float* __restrict__ pboxes,
                    const float* __restrict__ tboxes,
                    const float* __restrict__ iboxes,
                    const float* __restrict__ img,
                    const float* __restrict__ img_tgt,
                    const int*   __restrict__ tids,
                    float* __restrict__ outC,
                    float* __restrict__ outIoa)
{
    __shared__ float slog[QPB][128];   // staged logit gathers, [q_iter][lane]

    const int b    = blockIdx.y;
    const int q0   = blockIdx.x * QPB;
    const int lane = threadIdx.x;   // 0..99 -> targets, 100..107 -> ign boxes

    const bool isC   = (lane < TN);
    const bool isIoa = (lane >= TN) && (lane < TN + NIN);

    // per-batch image normalization (reciprocals)
    const float* im = img + b * 4;
    const float iw0 = __frcp_rn(im[0]);
    const float ih0 = __frcp_rn(im[1]);
    const float iw1 = __frcp_rn(im[2]);
    const float ih1 = __frcp_rn(im[3]);

    // hoist per-target (or per-ign) data into registers
    float tx0 = 0.f, ty0 = 0.f, tx1 = 0.f, ty1 = 0.f;
    float tnx0 = 0.f, tny0 = 0.f, tnx1 = 0.f, tny1 = 0.f;
    float tarea = 0.f;
    int   cls = 0;

    if (isC) {
        const int ti = b * TN + lane;
        const float4 tb = *reinterpret_cast<const float4*>(tboxes + ti * 4);
        tx0 = tb.x; ty0 = tb.y; tx1 = tb.z; ty1 = tb.w;
        const float4 it = *reinterpret_cast<const float4*>(img_tgt + ti * 4);
        tnx0 = tx0 * __frcp_rn(it.x);
        tny0 = ty0 * __frcp_rn(it.y);
        tnx1 = tx1 * __frcp_rn(it.z);
        tny1 = ty1 * __frcp_rn(it.w);
        tarea = (tx1 - tx0) * (ty1 - ty0);
        cls = tids[ti];
    } else if (isIoa) {
        const int ii = b * NIN + (lane - TN);
        const float4 ib = *reinterpret_cast<const float4*>(iboxes + ii * 4);
        tx0 = ib.x; ty0 = ib.y; tx1 = ib.z; ty1 = ib.w;
    }

    // ---- stage all QPB logit gathers via cp.async (MLP=10, no reg cost) ----
    // Each thread later reads ONLY its own staged word -> per-thread
    // cp.async.wait_group is sufficient; no __syncthreads required.
    if (isC) {
        const float* gl = logits + (size_t)(b * QN + q0) * NC + cls;
        #pragma unroll
        for (int i = 0; i < QPB; ++i) {
            uint32_t saddr = (uint32_t)__cvta_generic_to_shared(&slog[i][lane]);
            asm volatile("cp.async.ca.shared.global [%0], [%1], 4;\n"
                         :: "r"(saddr), "l"(gl + i * NC));
        }
    }
    asm volatile("cp.async.commit_group;\n");

    const float* pbox_base = pboxes + (size_t)(b * QN) * 4;
    float* outC_lane   = outC   + (size_t)(b * QN + q0) * TN  + lane;
    float* outIoa_lane = outIoa + (size_t)(b * QN + q0) * NIN + (lane - TN);

    // prefetch first pred box while copies are in flight
    float4 pb_n = *reinterpret_cast<const float4*>(pbox_base + q0 * 4);

    asm volatile("cp.async.wait_group 0;\n" ::: "memory");

    #pragma unroll
    for (int i = 0; i < QPB; ++i) {
        const float4 pb = pb_n;
        if (i + 1 < QPB)
            pb_n = *reinterpret_cast<const float4*>(pbox_base + (q0 + i + 1) * 4);

        const float px0 = pb.x, py0 = pb.y, px1 = pb.z, py1 = pb.w;
        const float parea = (px1 - px0) * (py1 - py0);

        if (isC) {
            // ---- focal class cost with a single log ----
            // e = exp(-x); p = 1/(1+e); -log(p) = log(1+e) = L; -log(1-p) = x + L
            const float x   = slog[i][lane];
            const float e   = __expf(-x);
            const float s   = 1.f + e;
            const float p   = __frcp_rn(s);   // independent of L: short chain
            const float L   = __logf(s);
            const float omp = 1.f - p;
            const float pos = 0.25f * omp * omp * L;
            const float neg = 0.75f * p * p * (x + L);
            const float cclass = pos - neg;

            // ---- L1 bbox cost on normalized boxes ----
            const float cb = fabsf(px0 * iw0 - tnx0)
                           + fabsf(py0 * ih0 - tny0)
                           + fabsf(px1 * iw1 - tnx1)
                           + fabsf(py1 * ih1 - tny1);

            // ---- GIoU with a single reciprocal ----
            const float ixw = fminf(px1, tx1) - fmaxf(px0, tx0);
            const float iyw = fminf(py1, ty1) - fmaxf(py0, ty0);
            const float inter = fmaxf(ixw, 0.f) * fmaxf(iyw, 0.f);
            const float uni = parea + tarea - inter;
            const float exw = fmaxf(px1, tx1) - fminf(px0, tx0);
            const float eyw = fmaxf(py1, ty1) - fminf(py0, ty0);
            const float enc = fmaxf(exw, 0.f) * fmaxf(eyw, 0.f);
            // giou = inter/uni + uni/enc - 1 = (inter*enc + uni*uni) / (uni*enc) - 1
            const float r    = __frcp_rn(uni * enc);
            const float giou = fmaf(inter * enc + uni * uni, r, -1.f);

            const float C = fmaf(5.f, cb, fmaf(2.f, cclass, -2.f * giou));
            outC_lane[i * TN] = C;
        } else if (isIoa) {
            const float ixw = fminf(px1, tx1) - fmaxf(px0, tx0);
            const float iyw = fminf(py1, ty1) - fmaxf(py0, ty0);
            const float inter = fmaxf(ixw, 0.f) * fmaxf(iyw, 0.f);
            outIoa_lane[i * NIN] = inter * __frcp_rn(parea);
        }
    }
}

extern "C" void kernel_launch(void* const* d_in, const int* in_sizes, int n_in,
                              void* d_out, int out_size)
{
    const float* logits  = (const float*)d_in[0];
    const float* pboxes  = (const float*)d_in[1];
    const float* tboxes  = (const float*)d_in[2];
    const float* iboxes  = (const float*)d_in[3];
    const float* img     = (const float*)d_in[4];
    const float* img_tgt = (const float*)d_in[5];
    const int*   tids    = (const int*)d_in[6];

    float* outC   = (float*)d_out;
    float* outIoa = (float*)d_out + (size_t)BSZ * QN * TN;

    dim3 grid(QN / QPB, BSZ);
    matcher_kernel<<<grid, 128>>>(logits, pboxes, tboxes, iboxes,
                                  img, img_tgt, tids, outC, outIoa);
}

// round 5
// speedup vs baseline: 1.0043x; 1.0043x over previous
#include <cuda_runtime.h>
#include <cuda_bf16.h>
#include <cstdint>

// HungarianMatcher cost computation, block-diagonal only.
// Shapes: BS=16, Q=1000, NC=80, T=100, NI=8
// Output: C_diag (BS,Q,T) followed by ioa_diag (BS,Q,NI), f32.

#define BSZ 16
#define QN  1000
#define NC  80
#define TN  100
#define NIN 8
#define QPB 10   // q rows per block
#define HALF 5   // q-pair stride: iteration i computes q0+i and q0+i+HALF

struct TgtRegs {
    float tx0, ty0, tx1, ty1;       // raw target / ign box
    float tnx0, tny0, tnx1, tny1;   // normalized target box
    float tarea;
};

// One C-cost element: focal class cost + L1 + GIoU. Pure FMA/MUFU, no loads.
__device__ __forceinline__ float cost_elem(const float4 pb, const float x,
                                           const TgtRegs& t,
                                           const float iw0, const float ih0,
                                           const float iw1, const float ih1)
{
    const float px0 = pb.x, py0 = pb.y, px1 = pb.z, py1 = pb.w;
    const float parea = (px1 - px0) * (py1 - py0);

    // focal class cost, single log:
    // e = exp(-x); p = 1/(1+e); -log(p) = log1p(e) = L; -log(1-p) = x + L
    const float e   = __expf(-x);
    const float s   = 1.f + e;
    const float p   = __frcp_rn(s);
    const float L   = __logf(s);
    const float omp = 1.f - p;
    const float pos = 0.25f * omp * omp * L;
    const float neg = 0.75f * p * p * (x + L);
    const float cclass = pos - neg;

    // L1 bbox cost on normalized boxes
    const float cb = fabsf(px0 * iw0 - t.tnx0)
                   + fabsf(py0 * ih0 - t.tny0)
                   + fabsf(px1 * iw1 - t.tnx1)
                   + fabsf(py1 * ih1 - t.tny1);

    // GIoU with a single reciprocal
    const float ixw = fminf(px1, t.tx1) - fmaxf(px0, t.tx0);
    const float iyw = fminf(py1, t.ty1) - fmaxf(py0, t.ty0);
    const float inter = fmaxf(ixw, 0.f) * fmaxf(iyw, 0.f);
    const float uni = parea + t.tarea - inter;
    const float exw = fmaxf(px1, t.tx1) - fminf(px0, t.tx0);
    const float eyw = fmaxf(py1, t.ty1) - fminf(py0, t.ty0);
    const float enc = fmaxf(exw, 0.f) * fmaxf(eyw, 0.f);
    // giou = inter/uni + uni/enc - 1 = (inter*enc + uni*uni)/(uni*enc) - 1
    const float r    = __frcp_rn(uni * enc);
    const float giou = fmaf(inter * enc + uni * uni, r, -1.f);

    return fmaf(5.f, cb, fmaf(2.f, cclass, -2.f * giou));
}

__device__ __forceinline__ float ioa_elem(const float4 pb, const TgtRegs& t)
{
    const float px0 = pb.x, py0 = pb.y, px1 = pb.z, py1 = pb.w;
    const float parea = (px1 - px0) * (py1 - py0);
    const float ixw = fminf(px1, t.tx1) - fmaxf(px0, t.tx0);
    const float iyw = fminf(py1, t.ty1) - fmaxf(py0, t.ty0);
    const float inter = fmaxf(ixw, 0.f) * fmaxf(iyw, 0.f);
    return inter * __frcp_rn(parea);
}

__global__ __launch_bounds__(128, 8)
void matcher_kernel(const float* __restrict__ logits,
                    const float* __restrict__ pboxes,
                    const float* __restrict__ tboxes,
                    const float* __restrict__ iboxes,
                    const float* __restrict__ img,
                    const float* __restrict__ img_tgt,
                    const int*   __restrict__ tids,
                    float* __restrict__ outC,
                    float* __restrict__ outIoa)
{
    __shared__ float slog[QPB][128];   // staged logit gathers, [q_iter][lane]

    const int b    = blockIdx.y;
    const int q0   = blockIdx.x * QPB;
    const int lane = threadIdx.x;   // 0..99 -> targets, 100..107 -> ign boxes

    const bool isC   = (lane < TN);
    const bool isIoa = (lane >= TN) && (lane < TN + NIN);

    // per-batch image normalization (reciprocals)
    const float* im = img + b * 4;
    const float iw0 = __frcp_rn(im[0]);
    const float ih0 = __frcp_rn(im[1]);
    const float iw1 = __frcp_rn(im[2]);
    const float ih1 = __frcp_rn(im[3]);

    TgtRegs t = {};
    int cls = 0;

    if (isC) {
        const int ti = b * TN + lane;
        const float4 tb = *reinterpret_cast<const float4*>(tboxes + ti * 4);
        t.tx0 = tb.x; t.ty0 = tb.y; t.tx1 = tb.z; t.ty1 = tb.w;
        const float4 it = *reinterpret_cast<const float4*>(img_tgt + ti * 4);
        t.tnx0 = t.tx0 * __frcp_rn(it.x);
        t.tny0 = t.ty0 * __frcp_rn(it.y);
        t.tnx1 = t.tx1 * __frcp_rn(it.z);
        t.tny1 = t.ty1 * __frcp_rn(it.w);
        t.tarea = (t.tx1 - t.tx0) * (t.ty1 - t.ty0);
        cls = tids[ti];
    } else if (isIoa) {
        const int ii = b * NIN + (lane - TN);
        const float4 ib = *reinterpret_cast<const float4*>(iboxes + ii * 4);
        t.tx0 = ib.x; t.ty0 = ib.y; t.tx1 = ib.z; t.ty1 = ib.w;
    }

    // stage all QPB logit gathers via cp.async (MLP=10, no reg cost);
    // each thread later reads only its own staged word -> per-thread wait OK
    if (isC) {
        const float* gl = logits + (size_t)(b * QN + q0) * NC + cls;
        #pragma unroll
        for (int i = 0; i < QPB; ++i) {
            uint32_t saddr = (uint32_t)__cvta_generic_to_shared(&slog[i][lane]);
            asm volatile("cp.async.ca.shared.global [%0], [%1], 4;\n"
                         :: "r"(saddr), "l"(gl + i * NC));
        }
    }
    asm volatile("cp.async.commit_group;\n");

    const float* pbox_base = pboxes + (size_t)(b * QN) * 4;
    float* outC_lane   = outC   + (size_t)(b * QN + q0) * TN  + lane;
    float* outIoa_lane = outIoa + (size_t)(b * QN + q0) * NIN + (lane - TN);

    // prefetch first q-pair's pred boxes while copies are in flight
    float4 pbA_n = *reinterpret_cast<const float4*>(pbox_base + (q0)        * 4);
    float4 pbB_n = *reinterpret_cast<const float4*>(pbox_base + (q0 + HALF) * 4);

    asm volatile("cp.async.wait_group 0;\n" ::: "memory");

    #pragma unroll
    for (int i = 0; i < HALF; ++i) {
        const float4 pbA = pbA_n;
        const float4 pbB = pbB_n;
        if (i + 1 < HALF) {
            pbA_n = *reinterpret_cast<const float4*>(pbox_base + (q0 + i + 1)        * 4);
            pbB_n = *reinterpret_cast<const float4*>(pbox_base + (q0 + i + 1 + HALF) * 4);
        }

        if (isC) {
            // two fully independent chains -> scheduler interleaves them,
            // covering the MUFU/FMA latency of each
            const float xA = slog[i][lane];
            const float xB = slog[i + HALF][lane];
            const float CA = cost_elem(pbA, xA, t, iw0, ih0, iw1, ih1);
            const float CB = cost_elem(pbB, xB, t, iw0, ih0, iw1, ih1);
            outC_lane[(i)        * TN] = CA;
            outC_lane[(i + HALF) * TN] = CB;
        } else if (isIoa) {
            outIoa_lane[(i)        * NIN] = ioa_elem(pbA, t);
            outIoa_lane[(i + HALF) * NIN] = ioa_elem(pbB, t);
        }
    }
}

extern "C" void kernel_launch(void* const* d_in, const int* in_sizes, int n_in,
                              void* d_out, int out_size)
{
    const float* logits  = (const float*)d_in[0];
    const float* pboxes  = (const float*)d_in[1];
    const float* tboxes  = (const float*)d_in[2];
    const float* iboxes  = (const float*)d_in[3];
    const float* img     = (const float*)d_in[4];
    const float* img_tgt = (const float*)d_in[5];
    const int*   tids    = (const int*)d_in[6];

    float* outC   = (float*)d_out;
    float* outIoa = (float*)d_out + (size_t)BSZ * QN * TN;

    dim3 grid(QN / QPB, BSZ);
    matcher_kernel<<<grid, 128>>>(logits, pboxes, tboxes, iboxes,
                                  img, img_tgt, tids, outC, outIoa);
}